// round 2
// baseline (speedup 1.0000x reference)
#include <cuda_runtime.h>

#define NPTS (512 * 512)
#define THREADS 128
#define BLOCKS 456   // 152 SMs * 3 CTAs/SM (smem-limited)

// shared layout (float offsets)
#define OFF_CP0 0          // 2*32*13  = 832   (sp0 * coef0)
#define OFF_SB0 832        // 2*32     = 64
#define OFF_CP1 896        // 32*32*13 = 13312 (sp1 * coef1)
#define OFF_SB1 14208      // 32*32    = 1024
#define OFF_CP2 15232      // 32*1*13  = 416   (sp2 * coef2)
#define OFF_SB2 15648      // 32       = 32
#define SMEM_FLOATS 15680  // 62720 bytes

__device__ __forceinline__ float sigmoidf_(float x) {
    return 1.0f / (1.0f + __expf(-x));
}

// One KAN layer: out[o] = sum_i sb[i,o]*silu(x_i) + sum_k B(x_i)_k * (sp*coef)[i,o,k]
// Uniform cubic B-spline: only 4 taps nonzero; closed form at t = frac(10*x).
template <int IN, int OUT>
__device__ __forceinline__ void kan_layer(const float* xin, float* xout,
                                          const float* __restrict__ sCp,
                                          const float* __restrict__ sSb)
{
    float acc[OUT];
#pragma unroll
    for (int o = 0; o < OUT; o++) acc[o] = 0.0f;

#pragma unroll 1
    for (int i = 0; i < IN; i++) {
        float x = xin[i];
        float u = x * 10.0f;                        // x / h
        bool inr = (u >= -3.0f) && (u < 13.0f);     // support of the 17-knot grid
        float uc = inr ? u : 0.0f;
        float f  = floorf(uc);
        float t  = uc - f;
        int   m  = (int)f + 3;                      // interval index 0..15

        const float C6 = 0.16666667f;
        float t2 = t * t, t3 = t2 * t;
        float omt = 1.0f - t;
        float b0 = omt * omt * omt * C6;            // B_{m-3}
        float b1 = (3.0f * t3 - 6.0f * t2 + 4.0f) * C6;   // B_{m-2}
        float b2 = ((3.0f - 3.0f * t) * t2 + 3.0f * t + 1.0f) * C6; // B_{m-1}
        float b3 = t3 * C6;                         // B_m
        if (!inr)   { b0 = 0.0f; b1 = 0.0f; b2 = 0.0f; b3 = 0.0f; }
        if (m < 3)  b0 = 0.0f;                      // basis index j = m-3+d must be in [0,12]
        if (m < 2)  b1 = 0.0f;
        if (m < 1)  b2 = 0.0f;
        if (m > 12) b3 = 0.0f;
        if (m > 13) b2 = 0.0f;
        if (m > 14) b1 = 0.0f;
        int j  = m - 3;
        int k0 = max(j, 0);
        int k1 = max(min(j + 1, 12), 0);
        int k2 = max(min(j + 2, 12), 0);
        int k3 = min(j + 3, 12);

        float base = x * sigmoidf_(x);              // silu

        const float* C = sCp + i * (OUT * 13);
        const float* S = sSb + i * OUT;
#pragma unroll
        for (int o = 0; o < OUT; o++) {
            float a = acc[o];
            a = fmaf(S[o], base, a);
            a = fmaf(b0, C[o * 13 + k0], a);
            a = fmaf(b1, C[o * 13 + k1], a);
            a = fmaf(b2, C[o * 13 + k2], a);
            a = fmaf(b3, C[o * 13 + k3], a);
            acc[o] = a;
        }
    }
#pragma unroll
    for (int o = 0; o < OUT; o++) xout[o] = acc[o];
}

__global__ void __launch_bounds__(THREADS, 3)
kan_forward(const float* __restrict__ coords,
            const float* __restrict__ coef0, const float* __restrict__ sb0, const float* __restrict__ sp0,
            const float* __restrict__ coef1, const float* __restrict__ sb1, const float* __restrict__ sp1,
            const float* __restrict__ coef2, const float* __restrict__ sb2, const float* __restrict__ sp2,
            const float* __restrict__ dbias,
            float* __restrict__ out)
{
    extern __shared__ float smem[];

    // cooperative weight staging; fold sp into coef (idx/13 == i*OUT+o)
    for (int idx = threadIdx.x; idx < 832;   idx += THREADS) smem[OFF_CP0 + idx] = sp0[idx / 13] * coef0[idx];
    for (int idx = threadIdx.x; idx < 13312; idx += THREADS) smem[OFF_CP1 + idx] = sp1[idx / 13] * coef1[idx];
    for (int idx = threadIdx.x; idx < 416;   idx += THREADS) smem[OFF_CP2 + idx] = sp2[idx / 13] * coef2[idx];
    for (int idx = threadIdx.x; idx < 64;    idx += THREADS) smem[OFF_SB0 + idx] = sb0[idx];
    for (int idx = threadIdx.x; idx < 1024;  idx += THREADS) smem[OFF_SB1 + idx] = sb1[idx];
    for (int idx = threadIdx.x; idx < 32;    idx += THREADS) smem[OFF_SB2 + idx] = sb2[idx];
    __syncthreads();

    float bias = dbias[0];
    int stride = gridDim.x * THREADS;
    for (int p = blockIdx.x * THREADS + threadIdx.x; p < NPTS; p += stride) {
        float2 c = reinterpret_cast<const float2*>(coords)[p];
        float h0[2] = { c.x, c.y };
        float h1[32], h2[32], lg[1];
        kan_layer<2, 32>(h0, h1, smem + OFF_CP0, smem + OFF_SB0);
        kan_layer<32, 32>(h1, h2, smem + OFF_CP1, smem + OFF_SB1);
        kan_layer<32, 1>(h2, lg, smem + OFF_CP2, smem + OFF_SB2);
        out[p] = sigmoidf_(lg[0] + bias);
    }
}

extern "C" void kernel_launch(void* const* d_in, const int* in_sizes, int n_in,
                              void* d_out, int out_size)
{
    // order: coords, grid0, coef0, sb0, sp0, grid1, coef1, sb1, sp1, grid2, coef2, sb2, sp2, density_bias
    const float* coords = (const float*)d_in[0];
    const float* coef0  = (const float*)d_in[2];
    const float* sb0    = (const float*)d_in[3];
    const float* sp0    = (const float*)d_in[4];
    const float* coef1  = (const float*)d_in[6];
    const float* sb1    = (const float*)d_in[7];
    const float* sp1    = (const float*)d_in[8];
    const float* coef2  = (const float*)d_in[10];
    const float* sb2    = (const float*)d_in[11];
    const float* sp2    = (const float*)d_in[12];
    const float* dbias  = (const float*)d_in[13];
    float* out = (float*)d_out;

    size_t smem_bytes = SMEM_FLOATS * sizeof(float);
    cudaFuncSetAttribute(kan_forward, cudaFuncAttributeMaxDynamicSharedMemorySize, (int)smem_bytes);
    kan_forward<<<BLOCKS, THREADS, smem_bytes>>>(coords,
                                                 coef0, sb0, sp0,
                                                 coef1, sb1, sp1,
                                                 coef2, sb2, sp2,
                                                 dbias, out);
}